// round 6
// baseline (speedup 1.0000x reference)
#include <cuda_runtime.h>
#include <cuda_bf16.h>
#include <cstdint>

// Problem dims
#define Bn 8
#define Cn 16
#define Dn 192
#define OCn 4
#define OHn 50
#define OWn 200
#define Kbig (Cn*Dn)   // 3072

// GEMM tile config
#define BM 128
#define BN 64
#define BK 32
#define APAD 8   // A smem row pad (stride 40 bf16)
#define BPAD 8   // B smem row pad (stride 72 bf16)

// Scratch (device globals — no runtime allocation allowed)
__device__ float g_Rt[Cn*Cn*Dn*Dn];                    //  Rt[i][(j,q)][n] = R[i][j][n][q]
__device__ float g_t [(size_t)Bn*Cn*Dn*Kbig];          //  t[b,i][m][(j,q)]
__device__ float g_y [(size_t)Bn*Cn*Dn*Dn];            //  y[b,i][m][n]
__device__ float g_u [(size_t)Bn*OCn*OHn*Kbig];        //  u[b,i][m][(j,q)]

// ---------------------------------------------------------------------------
// Transpose each 192x192 matrix of R:  Rt[i][j][q][n] = R[i][j][n][q]
// ---------------------------------------------------------------------------
__global__ void k_transpose(const float* __restrict__ R) {
    __shared__ float tile[32][33];
    const int mat = blockIdx.z;
    const float* __restrict__ src = R    + (size_t)mat * Dn * Dn;
    float* __restrict__       dst = g_Rt + (size_t)mat * Dn * Dn;
    const int x0 = blockIdx.x * 32, y0 = blockIdx.y * 32;
    const int tx = threadIdx.x, ty = threadIdx.y;     // 32 x 8
    #pragma unroll
    for (int r = 0; r < 32; r += 8)
        tile[ty + r][tx] = src[(size_t)(y0 + ty + r) * Dn + x0 + tx];
    __syncthreads();
    #pragma unroll
    for (int r = 0; r < 32; r += 8)
        dst[(size_t)(x0 + ty + r) * Dn + y0 + tx] = tile[tx][ty + r];
}

// ---------------------------------------------------------------------------
// bf16x3 helpers
// ---------------------------------------------------------------------------
__device__ __forceinline__ void f2bf(float v, __nv_bfloat16& h, __nv_bfloat16& l) {
    h = __float2bfloat16_rn(v);
    l = __float2bfloat16_rn(v - __bfloat162float(h));
}

__device__ __forceinline__ void mma_bf16(float* c, const unsigned* a, const unsigned* b) {
    asm volatile(
        "mma.sync.aligned.m16n8k16.row.col.f32.bf16.bf16.f32 "
        "{%0,%1,%2,%3}, {%4,%5,%6,%7}, {%8,%9}, {%0,%1,%2,%3};\n"
        : "+f"(c[0]), "+f"(c[1]), "+f"(c[2]), "+f"(c[3])
        : "r"(a[0]), "r"(a[1]), "r"(a[2]), "r"(a[3]), "r"(b[0]), "r"(b[1]));
}

__device__ __forceinline__ void ldsm4(unsigned* r, unsigned addr) {
    asm volatile("ldmatrix.sync.aligned.m8n8.x4.shared.b16 {%0,%1,%2,%3}, [%4];\n"
                 : "=r"(r[0]), "=r"(r[1]), "=r"(r[2]), "=r"(r[3]) : "r"(addr));
}
__device__ __forceinline__ void ldsm4t(unsigned* r, unsigned addr) {
    asm volatile("ldmatrix.sync.aligned.m8n8.x4.trans.shared.b16 {%0,%1,%2,%3}, [%4];\n"
                 : "=r"(r[0]), "=r"(r[1]), "=r"(r[2]), "=r"(r[3]) : "r"(addr));
}

// ---------------------------------------------------------------------------
// Tensor-core bf16x3 GEMM: C = A[MxK] * B[KxN], fp32 in/out, NN row-major.
// Block 128x64, 256 threads (8 warps as 4x2, warp tile 32x32), BK=32.
// IDENTICAL compute to the verified R3 kernel; single change: gmem loads for
// tile k+1 are prefetched into registers while tile k's MMAs run.
// ---------------------------------------------------------------------------
__device__ __forceinline__ void bgemm(
    const float* __restrict__ A, int lda,
    const float* __restrict__ Bp, int ldb,
    float* __restrict__ Cp, int ldc,
    int M, int N, int K)
{
    __shared__ __nv_bfloat16 sAh[BM][BK + APAD];
    __shared__ __nv_bfloat16 sAl[BM][BK + APAD];
    __shared__ __nv_bfloat16 sBh[BK][BN + BPAD];
    __shared__ __nv_bfloat16 sBl[BK][BN + BPAD];

    const int tid  = threadIdx.x;
    const int lane = tid & 31;
    const int warp = tid >> 5;
    const int wm = warp & 3;          // m-warp 0..3
    const int wn = warp >> 2;         // n-warp 0..1
    const int row0 = blockIdx.y * BM;
    const int col0 = blockIdx.x * BN;

    // gmem load mappings (float4-coalesced) — same as R3
    const int ar = tid >> 3;          // A: row 0..31 (+32p), 8 thr/row
    const int ac = (tid & 7) * 4;     // A: k col
    const int br = tid >> 4;          // B: k row 0..15 (+16p)
    const int bc = (tid & 15) * 4;    // B: n col

    float acc[2][4][4];
    #pragma unroll
    for (int t = 0; t < 2; ++t)
        #pragma unroll
        for (int n = 0; n < 4; ++n)
            #pragma unroll
            for (int e = 0; e < 4; ++e) acc[t][n][e] = 0.f;

    // ldmatrix source addresses — same as R3
    unsigned aAdH[2], aAdL[2], bAdH[2], bAdL[2];
    #pragma unroll
    for (int t = 0; t < 2; ++t) {
        int rr = wm * 32 + t * 16 + (lane & 15);
        int cc = (lane >> 4) * 8;
        aAdH[t] = (unsigned)__cvta_generic_to_shared(&sAh[rr][cc]);
        aAdL[t] = (unsigned)__cvta_generic_to_shared(&sAl[rr][cc]);
    }
    #pragma unroll
    for (int p = 0; p < 2; ++p) {
        int rr = (lane & 15);
        int cc = wn * 32 + p * 16 + (lane >> 4) * 8;
        bAdH[p] = (unsigned)__cvta_generic_to_shared(&sBh[rr][cc]);
        bAdL[p] = (unsigned)__cvta_generic_to_shared(&sBl[rr][cc]);
    }
    const unsigned aK1 = 16u * 2u;                  // +16 bf16 along row
    const unsigned bK1 = 16u * (BN + BPAD) * 2u;    // +16 k-rows

    // register prefetch buffers
    float4 av[4], bv[2];

    auto gload = [&](int kt) {
        #pragma unroll
        for (int p = 0; p < 4; ++p) {
            int gr = row0 + ar + p * 32;
            av[p] = (gr < M) ? *reinterpret_cast<const float4*>(&A[(size_t)gr * lda + kt + ac])
                             : make_float4(0.f, 0.f, 0.f, 0.f);
        }
        #pragma unroll
        for (int p = 0; p < 2; ++p) {
            int gc = col0 + bc;
            bv[p] = (gc < N) ? *reinterpret_cast<const float4*>(&Bp[(size_t)(kt + br + p * 16) * ldb + gc])
                             : make_float4(0.f, 0.f, 0.f, 0.f);
        }
    };

    auto sstore = [&]() {
        #pragma unroll
        for (int p = 0; p < 4; ++p) {
            int r = ar + p * 32;
            __nv_bfloat16 h0,l0,h1,l1,h2,l2,h3,l3;
            f2bf(av[p].x, h0, l0); f2bf(av[p].y, h1, l1);
            f2bf(av[p].z, h2, l2); f2bf(av[p].w, h3, l3);
            __nv_bfloat162 q;
            q.x = h0; q.y = h1; *reinterpret_cast<__nv_bfloat162*>(&sAh[r][ac])     = q;
            q.x = h2; q.y = h3; *reinterpret_cast<__nv_bfloat162*>(&sAh[r][ac + 2]) = q;
            q.x = l0; q.y = l1; *reinterpret_cast<__nv_bfloat162*>(&sAl[r][ac])     = q;
            q.x = l2; q.y = l3; *reinterpret_cast<__nv_bfloat162*>(&sAl[r][ac + 2]) = q;
        }
        #pragma unroll
        for (int p = 0; p < 2; ++p) {
            int r = br + p * 16;
            __nv_bfloat16 h0,l0,h1,l1,h2,l2,h3,l3;
            f2bf(bv[p].x, h0, l0); f2bf(bv[p].y, h1, l1);
            f2bf(bv[p].z, h2, l2); f2bf(bv[p].w, h3, l3);
            __nv_bfloat162 q;
            q.x = h0; q.y = h1; *reinterpret_cast<__nv_bfloat162*>(&sBh[r][bc])     = q;
            q.x = h2; q.y = h3; *reinterpret_cast<__nv_bfloat162*>(&sBh[r][bc + 2]) = q;
            q.x = l0; q.y = l1; *reinterpret_cast<__nv_bfloat162*>(&sBl[r][bc])     = q;
            q.x = l2; q.y = l3; *reinterpret_cast<__nv_bfloat162*>(&sBl[r][bc + 2]) = q;
        }
    };

    gload(0);                          // prime the register buffer

    for (int kt = 0; kt < K; kt += BK) {
        sstore();                      // regs (tile kt) -> smem
        __syncthreads();
        if (kt + BK < K) gload(kt + BK);   // prefetch next tile during MMA

        // ---- 2 k16 chunks, 3 mma passes each (hi*hi + hi*lo + lo*hi) ----
        #pragma unroll
        for (int kk = 0; kk < 2; ++kk) {
            unsigned ah[2][4], al[2][4], bh[2][4], bl[2][4];
            #pragma unroll
            for (int t = 0; t < 2; ++t) {
                ldsm4(ah[t], aAdH[t] + kk * aK1);
                ldsm4(al[t], aAdL[t] + kk * aK1);
            }
            #pragma unroll
            for (int p = 0; p < 2; ++p) {
                ldsm4t(bh[p], bAdH[p] + kk * bK1);
                ldsm4t(bl[p], bAdL[p] + kk * bK1);
            }
            #pragma unroll
            for (int t = 0; t < 2; ++t) {
                #pragma unroll
                for (int nt = 0; nt < 4; ++nt) {
                    const unsigned* Bh = &bh[nt >> 1][(nt & 1) * 2];
                    const unsigned* Bl = &bl[nt >> 1][(nt & 1) * 2];
                    mma_bf16(acc[t][nt], ah[t], Bh);   // hi*hi
                    mma_bf16(acc[t][nt], ah[t], Bl);   // hi*lo
                    mma_bf16(acc[t][nt], al[t], Bh);   // lo*hi
                }
            }
        }
        __syncthreads();
    }

    // ---- epilogue (fp32) — identical to R3 ----
    #pragma unroll
    for (int t = 0; t < 2; ++t) {
        int mB = row0 + wm * 32 + t * 16 + (lane >> 2);
        #pragma unroll
        for (int nt = 0; nt < 4; ++nt) {
            int nB = col0 + wn * 32 + nt * 8 + (lane & 3) * 2;
            float* c = acc[t][nt];
            if (mB < M) {
                if (nB     < N) Cp[(size_t)mB * ldc + nB]     = c[0];
                if (nB + 1 < N) Cp[(size_t)mB * ldc + nB + 1] = c[1];
            }
            if (mB + 8 < M) {
                if (nB     < N) Cp[(size_t)(mB + 8) * ldc + nB]     = c[2];
                if (nB + 1 < N) Cp[(size_t)(mB + 8) * ldc + nB + 1] = c[3];
            }
        }
    }
}

// ---------------------------------------------------------------------------
// Stage A1:  t[b,i][m][(j,q)] = R[i,j] @ x[b,j]
// ---------------------------------------------------------------------------
__global__ void __launch_bounds__(256) k_gemm_A1(const float* __restrict__ R,
                                                 const float* __restrict__ x) {
    const int z = blockIdx.z;
    const int j = z % Cn;
    const int i = (z / Cn) % Cn;
    const int b = z / (Cn * Cn);
    const float* A  = R   + (size_t)(i * Cn + j) * Dn * Dn;
    const float* Bp = x   + (size_t)(b * Cn + j) * Dn * Dn;
    float*       Cp = g_t + (size_t)(b * Cn + i) * Dn * Kbig + (size_t)j * Dn;
    bgemm(A, Dn, Bp, Dn, Cp, Kbig, Dn, Dn, Dn);
}

// ---------------------------------------------------------------------------
// Stage A2:  y[b,i] = t[b,i] [192x3072] @ Rt[i] [3072x192]
// ---------------------------------------------------------------------------
__global__ void __launch_bounds__(256) k_gemm_A2() {
    const int z = blockIdx.z;                 // b*Cn + i
    const int i = z % Cn;
    const float* A  = g_t  + (size_t)z * Dn * Kbig;
    const float* Bp = g_Rt + (size_t)i * Cn * Dn * Dn;
    float*       Cp = g_y  + (size_t)z * Dn * Dn;
    bgemm(A, Kbig, Bp, Dn, Cp, Dn, Dn, Dn, Kbig);
}

// ---------------------------------------------------------------------------
// Stage B1:  u[b,i][m][(j,q)] = P[i,j] @ y[b,j]
// ---------------------------------------------------------------------------
__global__ void __launch_bounds__(256) k_gemm_B1(const float* __restrict__ P) {
    const int z = blockIdx.z;                 // (b*OCn + i)*Cn + j
    const int j = z % Cn;
    const int i = (z / Cn) % OCn;
    const int b = z / (Cn * OCn);
    const float* A  = P   + (size_t)(i * Cn + j) * OHn * Dn;
    const float* Bp = g_y + (size_t)(b * Cn + j) * Dn * Dn;
    float*       Cp = g_u + (size_t)(b * OCn + i) * OHn * Kbig + (size_t)j * Dn;
    bgemm(A, Dn, Bp, Dn, Cp, Kbig, OHn, Dn, Dn);
}

// ---------------------------------------------------------------------------
// Stage B2:  out[b,i] = u[b,i] [50x3072] @ PT[i] [3072x200]
// ---------------------------------------------------------------------------
__global__ void __launch_bounds__(256) k_gemm_B2(const float* __restrict__ PT,
                                                 float* __restrict__ out) {
    const int z = blockIdx.z;                 // b*OCn + i
    const int i = z % OCn;
    const float* A  = g_u + (size_t)z * OHn * Kbig;
    const float* Bp = PT  + (size_t)i * Cn * Dn * OWn;
    float*       Cp = out + (size_t)z * OHn * OWn;
    bgemm(A, Kbig, Bp, OWn, Cp, OWn, OHn, OWn, Kbig);
}

// ---------------------------------------------------------------------------
extern "C" void kernel_launch(void* const* d_in, const int* in_sizes, int n_in,
                              void* d_out, int out_size) {
    const float* x  = (const float*)d_in[0];
    const float* R  = (const float*)d_in[1];
    const float* P  = (const float*)d_in[2];
    const float* PT = (const float*)d_in[3];
    float* out = (float*)d_out;

    k_transpose<<<dim3(6, 6, 256), dim3(32, 8)>>>(R);
    k_gemm_A1<<<dim3(3, 2, Bn * Cn * Cn), 256>>>(R, x);
    k_gemm_A2<<<dim3(3, 2, Bn * Cn), 256>>>();
    k_gemm_B1<<<dim3(3, 1, Bn * OCn * Cn), 256>>>(P);
    k_gemm_B2<<<dim3(4, 1, Bn * OCn), 256>>>(PT, out);
}

// round 7
// speedup vs baseline: 1.2923x; 1.2923x over previous
#include <cuda_runtime.h>
#include <cuda_bf16.h>
#include <cstdint>

// Problem dims
#define Bn 8
#define Cn 16
#define Dn 192
#define OCn 4
#define OHn 50
#define OWn 200
#define Kbig (Cn*Dn)   // 3072

// GEMM tile config
#define BM 128
#define BN 64
#define BK 16
#define AP 24    // A smem row stride (16 + 8 pad) bf16
#define BP 72    // B smem row stride (64 + 8 pad) bf16

// Scratch (device globals — no runtime allocation allowed)
__device__ float g_Rt[Cn*Cn*Dn*Dn];                    //  Rt[i][(j,q)][n] = R[i][j][n][q]
__device__ float g_t [(size_t)Bn*Cn*Dn*Kbig];          //  t[b,i][m][(j,q)]
__device__ float g_y [(size_t)Bn*Cn*Dn*Dn];            //  y[b,i][m][n]
__device__ float g_u [(size_t)Bn*OCn*OHn*Kbig];        //  u[b,i][m][(j,q)]

// ---------------------------------------------------------------------------
// Transpose each 192x192 matrix of R:  Rt[i][j][q][n] = R[i][j][n][q]
// ---------------------------------------------------------------------------
__global__ void k_transpose(const float* __restrict__ R) {
    __shared__ float tile[32][33];
    const int mat = blockIdx.z;
    const float* __restrict__ src = R    + (size_t)mat * Dn * Dn;
    float* __restrict__       dst = g_Rt + (size_t)mat * Dn * Dn;
    const int x0 = blockIdx.x * 32, y0 = blockIdx.y * 32;
    const int tx = threadIdx.x, ty = threadIdx.y;     // 32 x 8
    #pragma unroll
    for (int r = 0; r < 32; r += 8)
        tile[ty + r][tx] = src[(size_t)(y0 + ty + r) * Dn + x0 + tx];
    __syncthreads();
    #pragma unroll
    for (int r = 0; r < 32; r += 8)
        dst[(size_t)(x0 + ty + r) * Dn + y0 + tx] = tile[tx][ty + r];
}

// ---------------------------------------------------------------------------
// bf16x3 helpers
// ---------------------------------------------------------------------------
__device__ __forceinline__ void f2bf(float v, __nv_bfloat16& h, __nv_bfloat16& l) {
    h = __float2bfloat16_rn(v);
    l = __float2bfloat16_rn(v - __bfloat162float(h));
}

__device__ __forceinline__ void mma_bf16(float* c, const unsigned* a, const unsigned* b) {
    asm volatile(
        "mma.sync.aligned.m16n8k16.row.col.f32.bf16.bf16.f32 "
        "{%0,%1,%2,%3}, {%4,%5,%6,%7}, {%8,%9}, {%0,%1,%2,%3};\n"
        : "+f"(c[0]), "+f"(c[1]), "+f"(c[2]), "+f"(c[3])
        : "r"(a[0]), "r"(a[1]), "r"(a[2]), "r"(a[3]), "r"(b[0]), "r"(b[1]));
}

__device__ __forceinline__ void ldsm4(unsigned* r, unsigned addr) {
    asm volatile("ldmatrix.sync.aligned.m8n8.x4.shared.b16 {%0,%1,%2,%3}, [%4];\n"
                 : "=r"(r[0]), "=r"(r[1]), "=r"(r[2]), "=r"(r[3]) : "r"(addr));
}
__device__ __forceinline__ void ldsm4t(unsigned* r, unsigned addr) {
    asm volatile("ldmatrix.sync.aligned.m8n8.x4.trans.shared.b16 {%0,%1,%2,%3}, [%4];\n"
                 : "=r"(r[0]), "=r"(r[1]), "=r"(r[2]), "=r"(r[3]) : "r"(addr));
}

// ---------------------------------------------------------------------------
// Tensor-core bf16x3 GEMM: C = A[MxK] * B[KxN], fp32 in/out, NN row-major.
// Block 128x64, 256 threads (8 warps as 4x2, warp tile 32x32), BK=16.
// Double-buffered smem (33792 B static), ONE __syncthreads per K-tile:
//   sync -> LDG tile k+1 -> MMA tile k (stage k&1) -> STS tile k+1 (other stage)
// Compute arithmetic identical to the verified R3 kernel.
// ---------------------------------------------------------------------------
__device__ __forceinline__ void bgemm(
    const float* __restrict__ A, int lda,
    const float* __restrict__ Bp, int ldb,
    float* __restrict__ Cp, int ldc,
    int M, int N, int K)
{
    __shared__ __nv_bfloat16 sAh[2][BM][AP];
    __shared__ __nv_bfloat16 sAl[2][BM][AP];
    __shared__ __nv_bfloat16 sBh[2][BK][BP];
    __shared__ __nv_bfloat16 sBl[2][BK][BP];

    const int tid  = threadIdx.x;
    const int lane = tid & 31;
    const int warp = tid >> 5;
    const int wm = warp & 3;          // m-warp 0..3
    const int wn = warp >> 2;         // n-warp 0..1
    const int row0 = blockIdx.y * BM;
    const int col0 = blockIdx.x * BN;

    // gmem load mappings (float4-coalesced)
    const int ar = tid >> 2;          // A: row 0..63 (+64), 4 thr/row
    const int ac = (tid & 3) * 4;     // A: k col 0/4/8/12
    const int br = tid >> 4;          // B: k row 0..15
    const int bc = (tid & 15) * 4;    // B: n col

    float acc[2][4][4];
    #pragma unroll
    for (int t = 0; t < 2; ++t)
        #pragma unroll
        for (int n = 0; n < 4; ++n)
            #pragma unroll
            for (int e = 0; e < 4; ++e) acc[t][n][e] = 0.f;

    // ldmatrix source addresses (stage 0); stage 1 adds the array-half stride
    unsigned aAdH[2], aAdL[2], bAdH[2], bAdL[2];
    #pragma unroll
    for (int t = 0; t < 2; ++t) {
        int rr = wm * 32 + t * 16 + (lane & 15);
        int cc = (lane >> 4) * 8;
        aAdH[t] = (unsigned)__cvta_generic_to_shared(&sAh[0][rr][cc]);
        aAdL[t] = (unsigned)__cvta_generic_to_shared(&sAl[0][rr][cc]);
    }
    #pragma unroll
    for (int p = 0; p < 2; ++p) {
        int rr = (lane & 15);
        int cc = wn * 32 + p * 16 + (lane >> 4) * 8;
        bAdH[p] = (unsigned)__cvta_generic_to_shared(&sBh[0][rr][cc]);
        bAdL[p] = (unsigned)__cvta_generic_to_shared(&sBl[0][rr][cc]);
    }
    const unsigned aStg = BM * AP * 2u;   // 6144 B  (one stage of sAh / sAl)
    const unsigned bStg = BK * BP * 2u;   // 2304 B  (one stage of sBh / sBl)

    // register prefetch buffers (12 regs)
    float4 av[2], bv;

    auto gload = [&](int kt) {
        #pragma unroll
        for (int p = 0; p < 2; ++p) {
            int gr = row0 + ar + p * 64;
            av[p] = (gr < M) ? *reinterpret_cast<const float4*>(&A[(size_t)gr * lda + kt + ac])
                             : make_float4(0.f, 0.f, 0.f, 0.f);
        }
        int gc = col0 + bc;
        bv = (gc < N) ? *reinterpret_cast<const float4*>(&Bp[(size_t)(kt + br) * ldb + gc])
                      : make_float4(0.f, 0.f, 0.f, 0.f);
    };

    auto sstore = [&](int s) {
        #pragma unroll
        for (int p = 0; p < 2; ++p) {
            int r = ar + p * 64;
            __nv_bfloat16 h0,l0,h1,l1,h2,l2,h3,l3;
            f2bf(av[p].x, h0, l0); f2bf(av[p].y, h1, l1);
            f2bf(av[p].z, h2, l2); f2bf(av[p].w, h3, l3);
            __nv_bfloat162 q;
            q.x = h0; q.y = h1; *reinterpret_cast<__nv_bfloat162*>(&sAh[s][r][ac])     = q;
            q.x = h2; q.y = h3; *reinterpret_cast<__nv_bfloat162*>(&sAh[s][r][ac + 2]) = q;
            q.x = l0; q.y = l1; *reinterpret_cast<__nv_bfloat162*>(&sAl[s][r][ac])     = q;
            q.x = l2; q.y = l3; *reinterpret_cast<__nv_bfloat162*>(&sAl[s][r][ac + 2]) = q;
        }
        {
            __nv_bfloat16 h0,l0,h1,l1,h2,l2,h3,l3;
            f2bf(bv.x, h0, l0); f2bf(bv.y, h1, l1);
            f2bf(bv.z, h2, l2); f2bf(bv.w, h3, l3);
            __nv_bfloat162 q;
            q.x = h0; q.y = h1; *reinterpret_cast<__nv_bfloat162*>(&sBh[s][br][bc])     = q;
            q.x = h2; q.y = h3; *reinterpret_cast<__nv_bfloat162*>(&sBh[s][br][bc + 2]) = q;
            q.x = l0; q.y = l1; *reinterpret_cast<__nv_bfloat162*>(&sBl[s][br][bc])     = q;
            q.x = l2; q.y = l3; *reinterpret_cast<__nv_bfloat162*>(&sBl[s][br][bc + 2]) = q;
        }
    };

    const int niter = K / BK;
    gload(0);
    sstore(0);

    for (int it = 0; it < niter; ++it) {
        __syncthreads();   // stage (it&1) writes visible; prior reads of other stage complete
        if (it + 1 < niter) gload((it + 1) * BK);   // LDG latency hidden under MMAs

        const int s = it & 1;
        const unsigned aOff = s * aStg, bOff = s * bStg;
        unsigned ah[2][4], al[2][4], bh[2][4], bl[2][4];
        #pragma unroll
        for (int t = 0; t < 2; ++t) {
            ldsm4(ah[t], aAdH[t] + aOff);
            ldsm4(al[t], aAdL[t] + aOff);
        }
        #pragma unroll
        for (int p = 0; p < 2; ++p) {
            ldsm4t(bh[p], bAdH[p] + bOff);
            ldsm4t(bl[p], bAdL[p] + bOff);
        }
        #pragma unroll
        for (int t = 0; t < 2; ++t) {
            #pragma unroll
            for (int nt = 0; nt < 4; ++nt) {
                const unsigned* Bh = &bh[nt >> 1][(nt & 1) * 2];
                const unsigned* Bl = &bl[nt >> 1][(nt & 1) * 2];
                mma_bf16(acc[t][nt], ah[t], Bh);   // hi*hi
                mma_bf16(acc[t][nt], ah[t], Bl);   // hi*lo
                mma_bf16(acc[t][nt], al[t], Bh);   // lo*hi
            }
        }

        if (it + 1 < niter) sstore((it + 1) & 1);   // write OTHER stage; no extra sync
    }

    // ---- epilogue (fp32) — identical to R3 ----
    #pragma unroll
    for (int t = 0; t < 2; ++t) {
        int mB = row0 + wm * 32 + t * 16 + (lane >> 2);
        #pragma unroll
        for (int nt = 0; nt < 4; ++nt) {
            int nB = col0 + wn * 32 + nt * 8 + (lane & 3) * 2;
            float* c = acc[t][nt];
            if (mB < M) {
                if (nB     < N) Cp[(size_t)mB * ldc + nB]     = c[0];
                if (nB + 1 < N) Cp[(size_t)mB * ldc + nB + 1] = c[1];
            }
            if (mB + 8 < M) {
                if (nB     < N) Cp[(size_t)(mB + 8) * ldc + nB]     = c[2];
                if (nB + 1 < N) Cp[(size_t)(mB + 8) * ldc + nB + 1] = c[3];
            }
        }
    }
}

// ---------------------------------------------------------------------------
// Stage A1:  t[b,i][m][(j,q)] = R[i,j] @ x[b,j]
// ---------------------------------------------------------------------------
__global__ void __launch_bounds__(256) k_gemm_A1(const float* __restrict__ R,
                                                 const float* __restrict__ x) {
    const int z = blockIdx.z;
    const int j = z % Cn;
    const int i = (z / Cn) % Cn;
    const int b = z / (Cn * Cn);
    const float* A  = R   + (size_t)(i * Cn + j) * Dn * Dn;
    const float* Bp = x   + (size_t)(b * Cn + j) * Dn * Dn;
    float*       Cp = g_t + (size_t)(b * Cn + i) * Dn * Kbig + (size_t)j * Dn;
    bgemm(A, Dn, Bp, Dn, Cp, Kbig, Dn, Dn, Dn);
}

// ---------------------------------------------------------------------------
// Stage A2:  y[b,i] = t[b,i] [192x3072] @ Rt[i] [3072x192]
// ---------------------------------------------------------------------------
__global__ void __launch_bounds__(256) k_gemm_A2() {
    const int z = blockIdx.z;                 // b*Cn + i
    const int i = z % Cn;
    const float* A  = g_t  + (size_t)z * Dn * Kbig;
    const float* Bp = g_Rt + (size_t)i * Cn * Dn * Dn;
    float*       Cp = g_y  + (size_t)z * Dn * Dn;
    bgemm(A, Kbig, Bp, Dn, Cp, Dn, Dn, Dn, Kbig);
}

// ---------------------------------------------------------------------------
// Stage B1:  u[b,i][m][(j,q)] = P[i,j] @ y[b,j]
// ---------------------------------------------------------------------------
__global__ void __launch_bounds__(256) k_gemm_B1(const float* __restrict__ P) {
    const int z = blockIdx.z;                 // (b*OCn + i)*Cn + j
    const int j = z % Cn;
    const int i = (z / Cn) % OCn;
    const int b = z / (Cn * OCn);
    const float* A  = P   + (size_t)(i * Cn + j) * OHn * Dn;
    const float* Bp = g_y + (size_t)(b * Cn + j) * Dn * Dn;
    float*       Cp = g_u + (size_t)(b * OCn + i) * OHn * Kbig + (size_t)j * Dn;
    bgemm(A, Dn, Bp, Dn, Cp, Kbig, OHn, Dn, Dn);
}

// ---------------------------------------------------------------------------
// Stage B2:  out[b,i] = u[b,i] [50x3072] @ PT[i] [3072x200]
// ---------------------------------------------------------------------------
__global__ void __launch_bounds__(256) k_gemm_B2(const float* __restrict__ PT,
                                                 float* __restrict__ out) {
    const int z = blockIdx.z;                 // b*OCn + i
    const int i = z % OCn;
    const float* A  = g_u + (size_t)z * OHn * Kbig;
    const float* Bp = PT  + (size_t)i * Cn * Dn * OWn;
    float*       Cp = out + (size_t)z * OHn * OWn;
    bgemm(A, Kbig, Bp, OWn, Cp, OWn, OHn, OWn, Kbig);
}

// ---------------------------------------------------------------------------
extern "C" void kernel_launch(void* const* d_in, const int* in_sizes, int n_in,
                              void* d_out, int out_size) {
    const float* x  = (const float*)d_in[0];
    const float* R  = (const float*)d_in[1];
    const float* P  = (const float*)d_in[2];
    const float* PT = (const float*)d_in[3];
    float* out = (float*)d_out;

    k_transpose<<<dim3(6, 6, 256), dim3(32, 8)>>>(R);
    k_gemm_A1<<<dim3(3, 2, Bn * Cn * Cn), 256>>>(R, x);
    k_gemm_A2<<<dim3(3, 2, Bn * Cn), 256>>>();
    k_gemm_B1<<<dim3(3, 1, Bn * OCn * Cn), 256>>>(P);
    k_gemm_B2<<<dim3(4, 1, Bn * OCn), 256>>>(PT, out);
}

// round 9
// speedup vs baseline: 1.4690x; 1.1367x over previous
#include <cuda_runtime.h>
#include <cuda_bf16.h>
#include <cstdint>

// Problem dims
#define Bn 8
#define Cn 16
#define Dn 192
#define OCn 4
#define OHn 50
#define OWn 200
#define Kbig (Cn*Dn)   // 3072

typedef __nv_bfloat16 bf16;

// Scratch (fp32 device globals — IDENTICAL to verified R3/R6/R7; no bf16 globals)
__device__ float g_Rt[Cn*Cn*Dn*Dn];                    //  Rt[i][(j,q)][n] = R[i][j][n][q]
__device__ float g_t [(size_t)Bn*Cn*Dn*Kbig];          //  t[b,i][m][(j,q)]
__device__ float g_y [(size_t)Bn*Cn*Dn*Dn];            //  y[b,i][m][n]
__device__ float g_u [(size_t)Bn*OCn*OHn*Kbig];        //  u[b,i][m][(j,q)]

// ---------------------------------------------------------------------------
// Transpose each 192x192 matrix of R (verified)
// ---------------------------------------------------------------------------
__global__ void k_transpose(const float* __restrict__ R) {
    __shared__ float tile[32][33];
    const int mat = blockIdx.z;
    const float* __restrict__ src = R    + (size_t)mat * Dn * Dn;
    float* __restrict__       dst = g_Rt + (size_t)mat * Dn * Dn;
    const int x0 = blockIdx.x * 32, y0 = blockIdx.y * 32;
    const int tx = threadIdx.x, ty = threadIdx.y;     // 32 x 8
    #pragma unroll
    for (int r = 0; r < 32; r += 8)
        tile[ty + r][tx] = src[(size_t)(y0 + ty + r) * Dn + x0 + tx];
    __syncthreads();
    #pragma unroll
    for (int r = 0; r < 32; r += 8)
        dst[(size_t)(x0 + ty + r) * Dn + y0 + tx] = tile[tx][ty + r];
}

// ---------------------------------------------------------------------------
// helpers (verified)
// ---------------------------------------------------------------------------
__device__ __forceinline__ void f2bf(float v, bf16& h, bf16& l) {
    h = __float2bfloat16_rn(v);
    l = __float2bfloat16_rn(v - __bfloat162float(h));
}
__device__ __forceinline__ void mma_bf16(float* c, const unsigned* a, const unsigned* b) {
    asm volatile(
        "mma.sync.aligned.m16n8k16.row.col.f32.bf16.bf16.f32 "
        "{%0,%1,%2,%3}, {%4,%5,%6,%7}, {%8,%9}, {%0,%1,%2,%3};\n"
        : "+f"(c[0]), "+f"(c[1]), "+f"(c[2]), "+f"(c[3])
        : "r"(a[0]), "r"(a[1]), "r"(a[2]), "r"(a[3]), "r"(b[0]), "r"(b[1]));
}
__device__ __forceinline__ void ldsm4(unsigned* r, unsigned addr) {
    asm volatile("ldmatrix.sync.aligned.m8n8.x4.shared.b16 {%0,%1,%2,%3}, [%4];\n"
                 : "=r"(r[0]), "=r"(r[1]), "=r"(r[2]), "=r"(r[3]) : "r"(addr));
}
__device__ __forceinline__ void ldsm4t(unsigned* r, unsigned addr) {
    asm volatile("ldmatrix.sync.aligned.m8n8.x4.trans.shared.b16 {%0,%1,%2,%3}, [%4];\n"
                 : "=r"(r[0]), "=r"(r[1]), "=r"(r[2]), "=r"(r[3]) : "r"(addr));
}

// ===========================================================================
// A-stage GEMM: 192x96 CTA tile, 384 threads, 12 warps (32x48 warp tiles),
// BK=16, double-buffered static smem, one __syncthreads per K-tile.
// Same verified dataflow: LDG fp32 -> f2bf -> STS.32 -> ldsm -> 3x MMA.
// A smem: hi (cols 0-15) | lo (cols 16-31) | pad, row stride 40 (conflict-free).
// ===========================================================================
#define A_AP 40
#define A_BP 104

__device__ __forceinline__ void bgemmA(
    const float* __restrict__ A, int lda,
    const float* __restrict__ Bp, int ldb,
    float* __restrict__ Cp, int ldc,
    int M, int N, int K)
{
    __shared__ bf16 sA [2][192][A_AP];    // 30720 B
    __shared__ bf16 sBh[2][16][A_BP];     //  6656 B
    __shared__ bf16 sBl[2][16][A_BP];     //  6656 B  -> 44032 B total

    const int tid  = threadIdx.x;
    const int lane = tid & 31;
    const int warp = tid >> 5;
    const int wm = warp % 6;              // m strip 0..5
    const int wn = warp / 6;              // n half 0..1
    const int row0 = 0;                   // M = 192 exactly, one m-tile
    const int col0 = blockIdx.x * 96;

    // gmem load mappings
    const int arow = tid >> 1;            // A row 0..191
    const int ac   = (tid & 1) * 8;       // A k-offset 0 / 8 (8 elems via 2 float4)
    const int brow = tid / 24;            // B k-row 0..15
    const int bcol = (tid % 24) * 4;      // B n-col (4 elems via 1 float4)

    float acc[2][6][4];
    #pragma unroll
    for (int t = 0; t < 2; ++t)
        #pragma unroll
        for (int n = 0; n < 6; ++n)
            #pragma unroll
            for (int e = 0; e < 4; ++e) acc[t][n][e] = 0.f;

    // ldmatrix base addresses (stage 0)
    unsigned aAd[2], bAdH[3], bAdL[3];
    #pragma unroll
    for (int t = 0; t < 2; ++t) {
        int rr = wm * 32 + t * 16 + (lane & 15);
        int cc = (lane >> 4) * 8;
        aAd[t] = (unsigned)__cvta_generic_to_shared(&sA[0][rr][cc]);
    }
    #pragma unroll
    for (int f = 0; f < 3; ++f) {
        int rr = lane & 15;
        int cc = wn * 48 + f * 16 + (lane >> 4) * 8;
        bAdH[f] = (unsigned)__cvta_generic_to_shared(&sBh[0][rr][cc]);
        bAdL[f] = (unsigned)__cvta_generic_to_shared(&sBl[0][rr][cc]);
    }
    const unsigned aStg = 192u * A_AP * 2u;   // bytes per A stage
    const unsigned bStg = 16u * A_BP * 2u;    // bytes per B stage

    float4 av[2], bv;

    auto gload = [&](int kt) {
        int gr = min(row0 + arow, M - 1);
        #pragma unroll
        for (int p = 0; p < 2; ++p)
            av[p] = *reinterpret_cast<const float4*>(&A[(size_t)gr * lda + kt + ac + p * 4]);
        int gc = min(col0 + bcol, N - 4);
        bv = *reinterpret_cast<const float4*>(&Bp[(size_t)(kt + brow) * ldb + gc]);
    };

    auto sstore = [&](int s) {
        #pragma unroll
        for (int p = 0; p < 2; ++p) {
            bf16 h0,l0,h1,l1,h2,l2,h3,l3;
            f2bf(av[p].x, h0, l0); f2bf(av[p].y, h1, l1);
            f2bf(av[p].z, h2, l2); f2bf(av[p].w, h3, l3);
            __nv_bfloat162 q;
            int c = ac + p * 4;
            q.x = h0; q.y = h1; *reinterpret_cast<__nv_bfloat162*>(&sA[s][arow][c])          = q;
            q.x = h2; q.y = h3; *reinterpret_cast<__nv_bfloat162*>(&sA[s][arow][c + 2])      = q;
            q.x = l0; q.y = l1; *reinterpret_cast<__nv_bfloat162*>(&sA[s][arow][16 + c])     = q;
            q.x = l2; q.y = l3; *reinterpret_cast<__nv_bfloat162*>(&sA[s][arow][16 + c + 2]) = q;
        }
        {
            bf16 h0,l0,h1,l1,h2,l2,h3,l3;
            f2bf(bv.x, h0, l0); f2bf(bv.y, h1, l1);
            f2bf(bv.z, h2, l2); f2bf(bv.w, h3, l3);
            __nv_bfloat162 q;
            q.x = h0; q.y = h1; *reinterpret_cast<__nv_bfloat162*>(&sBh[s][brow][bcol])     = q;
            q.x = h2; q.y = h3; *reinterpret_cast<__nv_bfloat162*>(&sBh[s][brow][bcol + 2]) = q;
            q.x = l0; q.y = l1; *reinterpret_cast<__nv_bfloat162*>(&sBl[s][brow][bcol])     = q;
            q.x = l2; q.y = l3; *reinterpret_cast<__nv_bfloat162*>(&sBl[s][brow][bcol + 2]) = q;
        }
    };

    const int niter = K / 16;
    gload(0);
    sstore(0);

    for (int it = 0; it < niter; ++it) {
        __syncthreads();
        if (it + 1 < niter) gload((it + 1) * 16);   // hidden under MMAs

        const int s = it & 1;
        const unsigned aOff = s * aStg, bOff = s * bStg;

        unsigned ah[2][4], al[2][4], bh[3][4], bl[3][4];
        #pragma unroll
        for (int t = 0; t < 2; ++t) {
            ldsm4(ah[t], aAd[t] + aOff);            // hi at col 0
            ldsm4(al[t], aAd[t] + aOff + 32);       // lo at col 16 (+32 B)
        }
        #pragma unroll
        for (int f = 0; f < 3; ++f) {
            ldsm4t(bh[f], bAdH[f] + bOff);
            ldsm4t(bl[f], bAdL[f] + bOff);
        }
        #pragma unroll
        for (int t = 0; t < 2; ++t) {
            #pragma unroll
            for (int nt = 0; nt < 6; ++nt) {
                const unsigned* Bh = &bh[nt >> 1][(nt & 1) * 2];
                const unsigned* Bl = &bl[nt >> 1][(nt & 1) * 2];
                mma_bf16(acc[t][nt], ah[t], Bh);   // hi*hi
                mma_bf16(acc[t][nt], ah[t], Bl);   // hi*lo
                mma_bf16(acc[t][nt], al[t], Bh);   // lo*hi
            }
        }

        if (it + 1 < niter) sstore((it + 1) & 1);   // other stage; no extra sync
    }

    // epilogue (fp32)
    #pragma unroll
    for (int t = 0; t < 2; ++t) {
        int mB = row0 + wm * 32 + t * 16 + (lane >> 2);
        #pragma unroll
        for (int nt = 0; nt < 6; ++nt) {
            int nB = col0 + wn * 48 + nt * 8 + (lane & 3) * 2;
            float* c = acc[t][nt];
            #pragma unroll
            for (int e = 0; e < 4; ++e) {
                int gm = mB + (e >> 1) * 8;
                int gn = nB + (e & 1);
                if (gm < M && gn < N)
                    Cp[(size_t)gm * ldc + gn] = c[e];
            }
        }
    }
}

// ===========================================================================
// B-stage GEMM: EXACT verified R7 kernel (128x64, 256 thr, BK=16, dbl-buffer)
// ===========================================================================
#define BM 128
#define BN 64
#define AP 24
#define BP 72

__device__ __forceinline__ void bgemm(
    const float* __restrict__ A, int lda,
    const float* __restrict__ Bp, int ldb,
    float* __restrict__ Cp, int ldc,
    int M, int N, int K)
{
    __shared__ bf16 sAh[2][BM][AP];
    __shared__ bf16 sAl[2][BM][AP];
    __shared__ bf16 sBh[2][16][BP];
    __shared__ bf16 sBl[2][16][BP];

    const int tid  = threadIdx.x;
    const int lane = tid & 31;
    const int warp = tid >> 5;
    const int wm = warp & 3;
    const int wn = warp >> 2;
    const int row0 = blockIdx.y * BM;
    const int col0 = blockIdx.x * BN;

    const int ar = tid >> 2;
    const int ac = (tid & 3) * 4;
    const int br = tid >> 4;
    const int bc = (tid & 15) * 4;

    float acc[2][4][4];
    #pragma unroll
    for (int t = 0; t < 2; ++t)
        #pragma unroll
        for (int n = 0; n < 4; ++n)
            #pragma unroll
            for (int e = 0; e < 4; ++e) acc[t][n][e] = 0.f;

    unsigned aAdH[2], aAdL[2], bAdH[2], bAdL[2];
    #pragma unroll
    for (int t = 0; t < 2; ++t) {
        int rr = wm * 32 + t * 16 + (lane & 15);
        int cc = (lane >> 4) * 8;
        aAdH[t] = (unsigned)__cvta_generic_to_shared(&sAh[0][rr][cc]);
        aAdL[t] = (unsigned)__cvta_generic_to_shared(&sAl[0][rr][cc]);
    }
    #pragma unroll
    for (int p = 0; p < 2; ++p) {
        int rr = (lane & 15);
        int cc = wn * 32 + p * 16 + (lane >> 4) * 8;
        bAdH[p] = (unsigned)__cvta_generic_to_shared(&sBh[0][rr][cc]);
        bAdL[p] = (unsigned)__cvta_generic_to_shared(&sBl[0][rr][cc]);
    }
    const unsigned aStg = BM * AP * 2u;
    const unsigned bStg = 16 * BP * 2u;

    float4 av[2], bv;

    auto gload = [&](int kt) {
        #pragma unroll
        for (int p = 0; p < 2; ++p) {
            int gr = row0 + ar + p * 64;
            av[p] = (gr < M) ? *reinterpret_cast<const float4*>(&A[(size_t)gr * lda + kt + ac])
                             : make_float4(0.f, 0.f, 0.f, 0.f);
        }
        int gc = col0 + bc;
        bv = (gc < N) ? *reinterpret_cast<const float4*>(&Bp[(size_t)(kt + br) * ldb + gc])
                      : make_float4(0.f, 0.f, 0.f, 0.f);
    };

    auto sstore = [&](int s) {
        #pragma unroll
        for (int p = 0; p < 2; ++p) {
            int r = ar + p * 64;
            bf16 h0,l0,h1,l1,h2,l2,h3,l3;
            f2bf(av[p].x, h0, l0); f2bf(av[p].y, h1, l1);
            f2bf(av[p].z, h2, l2); f2bf(av[p].w, h3, l3);
            __nv_bfloat162 q;
            q.x = h0; q.y = h1; *reinterpret_cast<__nv_bfloat162*>(&sAh[s][r][ac])     = q;
            q.x = h2; q.y = h3; *reinterpret_cast<__nv_bfloat162*>(&sAh[s][r][ac + 2]) = q;
            q.x = l0; q.y = l1; *reinterpret_cast<__nv_bfloat162*>(&sAl[s][r][ac])     = q;
            q.x = l2; q.y = l3; *reinterpret_cast<__nv_bfloat162*>(&sAl[s][r][ac + 2]) = q;
        }
        {
            bf16 h0,l0,h1,l1,h2,l2,h3,l3;
            f2bf(bv.x, h0, l0); f2bf(bv.y, h1, l1);
            f2bf(bv.z, h2, l2); f2bf(bv.w, h3, l3);
            __nv_bfloat162 q;
            q.x = h0; q.y = h1; *reinterpret_cast<__nv_bfloat162*>(&sBh[s][br][bc])     = q;
            q.x = h2; q.y = h3; *reinterpret_cast<__nv_bfloat162*>(&sBh[s][br][bc + 2]) = q;
            q.x = l0; q.y = l1; *reinterpret_cast<__nv_bfloat162*>(&sBl[s][br][bc])     = q;
            q.x = l2; q.y = l3; *reinterpret_cast<__nv_bfloat162*>(&sBl[s][br][bc + 2]) = q;
        }
    };

    const int niter = K / 16;
    gload(0);
    sstore(0);

    for (int it = 0; it < niter; ++it) {
        __syncthreads();
        if (it + 1 < niter) gload((it + 1) * 16);

        const int s = it & 1;
        const unsigned aOff = s * aStg, bOff = s * bStg;
        unsigned ah[2][4], al[2][4], bh[2][4], bl[2][4];
        #pragma unroll
        for (int t = 0; t < 2; ++t) {
            ldsm4(ah[t], aAdH[t] + aOff);
            ldsm4(al[t], aAdL[t] + aOff);
        }
        #pragma unroll
        for (int p = 0; p < 2; ++p) {
            ldsm4t(bh[p], bAdH[p] + bOff);
            ldsm4t(bl[p], bAdL[p] + bOff);
        }
        #pragma unroll
        for (int t = 0; t < 2; ++t) {
            #pragma unroll
            for (int nt = 0; nt < 4; ++nt) {
                const unsigned* Bh = &bh[nt >> 1][(nt & 1) * 2];
                const unsigned* Bl = &bl[nt >> 1][(nt & 1) * 2];
                mma_bf16(acc[t][nt], ah[t], Bh);
                mma_bf16(acc[t][nt], ah[t], Bl);
                mma_bf16(acc[t][nt], al[t], Bh);
            }
        }

        if (it + 1 < niter) sstore((it + 1) & 1);
    }

    #pragma unroll
    for (int t = 0; t < 2; ++t) {
        int mB = row0 + wm * 32 + t * 16 + (lane >> 2);
        #pragma unroll
        for (int nt = 0; nt < 4; ++nt) {
            int nB = col0 + wn * 32 + nt * 8 + (lane & 3) * 2;
            float* c = acc[t][nt];
            if (mB < M) {
                if (nB     < N) Cp[(size_t)mB * ldc + nB]     = c[0];
                if (nB + 1 < N) Cp[(size_t)mB * ldc + nB + 1] = c[1];
            }
            if (mB + 8 < M) {
                if (nB     < N) Cp[(size_t)(mB + 8) * ldc + nB]     = c[2];
                if (nB + 1 < N) Cp[(size_t)(mB + 8) * ldc + nB + 1] = c[3];
            }
        }
    }
}

// ---------------------------------------------------------------------------
// Stage kernels
// ---------------------------------------------------------------------------
__global__ void __launch_bounds__(384) k_gemm_A1(const float* __restrict__ R,
                                                 const float* __restrict__ x) {
    const int z = blockIdx.z;
    const int j = z % Cn;
    const int i = (z / Cn) % Cn;
    const int b = z / (Cn * Cn);
    const float* A  = R   + (size_t)(i * Cn + j) * Dn * Dn;
    const float* Bp = x   + (size_t)(b * Cn + j) * Dn * Dn;
    float*       Cp = g_t + (size_t)(b * Cn + i) * Dn * Kbig + (size_t)j * Dn;
    bgemmA(A, Dn, Bp, Dn, Cp, Kbig, Dn, Dn, Dn);
}

__global__ void __launch_bounds__(384) k_gemm_A2() {
    const int z = blockIdx.z;                 // b*Cn + i
    const int i = z % Cn;
    const float* A  = g_t  + (size_t)z * Dn * Kbig;
    const float* Bp = g_Rt + (size_t)i * Cn * Dn * Dn;
    float*       Cp = g_y  + (size_t)z * Dn * Dn;
    bgemmA(A, Kbig, Bp, Dn, Cp, Dn, Dn, Dn, Kbig);
}

__global__ void __launch_bounds__(256) k_gemm_B1(const float* __restrict__ P) {
    const int z = blockIdx.z;                 // (b*OCn + i)*Cn + j
    const int j = z % Cn;
    const int i = (z / Cn) % OCn;
    const int b = z / (Cn * OCn);
    const float* A  = P   + (size_t)(i * Cn + j) * OHn * Dn;
    const float* Bp = g_y + (size_t)(b * Cn + j) * Dn * Dn;
    float*       Cp = g_u + (size_t)(b * OCn + i) * OHn * Kbig + (size_t)j * Dn;
    bgemm(A, Dn, Bp, Dn, Cp, Kbig, OHn, Dn, Dn);
}

__global__ void __launch_bounds__(256) k_gemm_B2(const float* __restrict__ PT,
                                                 float* __restrict__ out) {
    const int z = blockIdx.z;                 // b*OCn + i
    const int i = z % OCn;
    const float* A  = g_u + (size_t)z * OHn * Kbig;
    const float* Bp = PT  + (size_t)i * Cn * Dn * OWn;
    float*       Cp = out + (size_t)z * OHn * OWn;
    bgemm(A, Kbig, Bp, OWn, Cp, OWn, OHn, OWn, Kbig);
}

// ---------------------------------------------------------------------------
extern "C" void kernel_launch(void* const* d_in, const int* in_sizes, int n_in,
                              void* d_out, int out_size) {
    const float* x  = (const float*)d_in[0];
    const float* R  = (const float*)d_in[1];
    const float* P  = (const float*)d_in[2];
    const float* PT = (const float*)d_in[3];
    float* out = (float*)d_out;

    k_transpose<<<dim3(6, 6, 256), dim3(32, 8)>>>(R);
    k_gemm_A1<<<dim3(2, 1, Bn * Cn * Cn), 384>>>(R, x);
    k_gemm_A2<<<dim3(2, 1, Bn * Cn), 384>>>();
    k_gemm_B1<<<dim3(3, 1, Bn * OCn * Cn), 256>>>(P);
    k_gemm_B2<<<dim3(4, 1, Bn * OCn), 256>>>(PT, out);
}

// round 11
// speedup vs baseline: 1.6179x; 1.1014x over previous
#include <cuda_runtime.h>
#include <cuda_bf16.h>
#include <cstdint>

// Problem dims
#define Bn 8
#define Cn 16
#define Dn 192
#define OCn 4
#define OHn 50
#define OWn 200
#define Kbig (Cn*Dn)   // 3072

typedef __nv_bfloat16 bf16;

// Scratch (fp32 device globals — verified class)
__device__ float g_Rt[Cn*Cn*Dn*Dn];                    //  Rt[i][(j,q)][n] = R[i][j][n][q]
__device__ float g_t [(size_t)Bn*Cn*Dn*Kbig];          //  t[b,i][m][(j,q)]
__device__ float g_y [(size_t)Bn*Cn*Dn*Dn];            //  y[b,i][m][n]
__device__ float g_u [(size_t)Bn*OCn*OHn*Kbig];        //  u[b,i][m][(j,q)]
__device__ float g_p [(size_t)4*Bn*OCn*OHn*OWn];       //  B2 split-K partials

// ---------------------------------------------------------------------------
// Transpose each 192x192 matrix of R (verified)
// ---------------------------------------------------------------------------
__global__ void k_transpose(const float* __restrict__ R) {
    __shared__ float tile[32][33];
    const int mat = blockIdx.z;
    const float* __restrict__ src = R    + (size_t)mat * Dn * Dn;
    float* __restrict__       dst = g_Rt + (size_t)mat * Dn * Dn;
    const int x0 = blockIdx.x * 32, y0 = blockIdx.y * 32;
    const int tx = threadIdx.x, ty = threadIdx.y;     // 32 x 8
    #pragma unroll
    for (int r = 0; r < 32; r += 8)
        tile[ty + r][tx] = src[(size_t)(y0 + ty + r) * Dn + x0 + tx];
    __syncthreads();
    #pragma unroll
    for (int r = 0; r < 32; r += 8)
        dst[(size_t)(x0 + ty + r) * Dn + y0 + tx] = tile[tx][ty + r];
}

// ---------------------------------------------------------------------------
// helpers (verified)
// ---------------------------------------------------------------------------
__device__ __forceinline__ void f2bf(float v, bf16& h, bf16& l) {
    h = __float2bfloat16_rn(v);
    l = __float2bfloat16_rn(v - __bfloat162float(h));
}
__device__ __forceinline__ void mma_bf16(float* c, const unsigned* a, const unsigned* b) {
    asm volatile(
        "mma.sync.aligned.m16n8k16.row.col.f32.bf16.bf16.f32 "
        "{%0,%1,%2,%3}, {%4,%5,%6,%7}, {%8,%9}, {%0,%1,%2,%3};\n"
        : "+f"(c[0]), "+f"(c[1]), "+f"(c[2]), "+f"(c[3])
        : "r"(a[0]), "r"(a[1]), "r"(a[2]), "r"(a[3]), "r"(b[0]), "r"(b[1]));
}
__device__ __forceinline__ void ldsm4(unsigned* r, unsigned addr) {
    asm volatile("ldmatrix.sync.aligned.m8n8.x4.shared.b16 {%0,%1,%2,%3}, [%4];\n"
                 : "=r"(r[0]), "=r"(r[1]), "=r"(r[2]), "=r"(r[3]) : "r"(addr));
}
__device__ __forceinline__ void ldsm4t(unsigned* r, unsigned addr) {
    asm volatile("ldmatrix.sync.aligned.m8n8.x4.trans.shared.b16 {%0,%1,%2,%3}, [%4];\n"
                 : "=r"(r[0]), "=r"(r[1]), "=r"(r[2]), "=r"(r[3]) : "r"(addr));
}

// ===========================================================================
// A-stage GEMM: 192x96 CTA tile, 384 threads — VERIFIED R9, unchanged.
// ===========================================================================
#define A_AP 40
#define A_BP 104

__device__ __forceinline__ void bgemmA(
    const float* __restrict__ A, int lda,
    const float* __restrict__ Bp, int ldb,
    float* __restrict__ Cp, int ldc,
    int M, int N, int K)
{
    __shared__ bf16 sA [2][192][A_AP];
    __shared__ bf16 sBh[2][16][A_BP];
    __shared__ bf16 sBl[2][16][A_BP];

    const int tid  = threadIdx.x;
    const int lane = tid & 31;
    const int warp = tid >> 5;
    const int wm = warp % 6;
    const int wn = warp / 6;
    const int row0 = 0;
    const int col0 = blockIdx.x * 96;

    const int arow = tid >> 1;
    const int ac   = (tid & 1) * 8;
    const int brow = tid / 24;
    const int bcol = (tid % 24) * 4;

    float acc[2][6][4];
    #pragma unroll
    for (int t = 0; t < 2; ++t)
        #pragma unroll
        for (int n = 0; n < 6; ++n)
            #pragma unroll
            for (int e = 0; e < 4; ++e) acc[t][n][e] = 0.f;

    unsigned aAd[2], bAdH[3], bAdL[3];
    #pragma unroll
    for (int t = 0; t < 2; ++t) {
        int rr = wm * 32 + t * 16 + (lane & 15);
        int cc = (lane >> 4) * 8;
        aAd[t] = (unsigned)__cvta_generic_to_shared(&sA[0][rr][cc]);
    }
    #pragma unroll
    for (int f = 0; f < 3; ++f) {
        int rr = lane & 15;
        int cc = wn * 48 + f * 16 + (lane >> 4) * 8;
        bAdH[f] = (unsigned)__cvta_generic_to_shared(&sBh[0][rr][cc]);
        bAdL[f] = (unsigned)__cvta_generic_to_shared(&sBl[0][rr][cc]);
    }
    const unsigned aStg = 192u * A_AP * 2u;
    const unsigned bStg = 16u * A_BP * 2u;

    float4 av[2], bv;

    auto gload = [&](int kt) {
        int gr = min(row0 + arow, M - 1);
        #pragma unroll
        for (int p = 0; p < 2; ++p)
            av[p] = *reinterpret_cast<const float4*>(&A[(size_t)gr * lda + kt + ac + p * 4]);
        int gc = min(col0 + bcol, N - 4);
        bv = *reinterpret_cast<const float4*>(&Bp[(size_t)(kt + brow) * ldb + gc]);
    };

    auto sstore = [&](int s) {
        #pragma unroll
        for (int p = 0; p < 2; ++p) {
            bf16 h0,l0,h1,l1,h2,l2,h3,l3;
            f2bf(av[p].x, h0, l0); f2bf(av[p].y, h1, l1);
            f2bf(av[p].z, h2, l2); f2bf(av[p].w, h3, l3);
            __nv_bfloat162 q;
            int c = ac + p * 4;
            q.x = h0; q.y = h1; *reinterpret_cast<__nv_bfloat162*>(&sA[s][arow][c])          = q;
            q.x = h2; q.y = h3; *reinterpret_cast<__nv_bfloat162*>(&sA[s][arow][c + 2])      = q;
            q.x = l0; q.y = l1; *reinterpret_cast<__nv_bfloat162*>(&sA[s][arow][16 + c])     = q;
            q.x = l2; q.y = l3; *reinterpret_cast<__nv_bfloat162*>(&sA[s][arow][16 + c + 2]) = q;
        }
        {
            bf16 h0,l0,h1,l1,h2,l2,h3,l3;
            f2bf(bv.x, h0, l0); f2bf(bv.y, h1, l1);
            f2bf(bv.z, h2, l2); f2bf(bv.w, h3, l3);
            __nv_bfloat162 q;
            q.x = h0; q.y = h1; *reinterpret_cast<__nv_bfloat162*>(&sBh[s][brow][bcol])     = q;
            q.x = h2; q.y = h3; *reinterpret_cast<__nv_bfloat162*>(&sBh[s][brow][bcol + 2]) = q;
            q.x = l0; q.y = l1; *reinterpret_cast<__nv_bfloat162*>(&sBl[s][brow][bcol])     = q;
            q.x = l2; q.y = l3; *reinterpret_cast<__nv_bfloat162*>(&sBl[s][brow][bcol + 2]) = q;
        }
    };

    const int niter = K / 16;
    gload(0);
    sstore(0);

    for (int it = 0; it < niter; ++it) {
        __syncthreads();
        if (it + 1 < niter) gload((it + 1) * 16);

        const int s = it & 1;
        const unsigned aOff = s * aStg, bOff = s * bStg;

        unsigned ah[2][4], al[2][4], bh[3][4], bl[3][4];
        #pragma unroll
        for (int t = 0; t < 2; ++t) {
            ldsm4(ah[t], aAd[t] + aOff);
            ldsm4(al[t], aAd[t] + aOff + 32);
        }
        #pragma unroll
        for (int f = 0; f < 3; ++f) {
            ldsm4t(bh[f], bAdH[f] + bOff);
            ldsm4t(bl[f], bAdL[f] + bOff);
        }
        #pragma unroll
        for (int t = 0; t < 2; ++t) {
            #pragma unroll
            for (int nt = 0; nt < 6; ++nt) {
                const unsigned* Bh = &bh[nt >> 1][(nt & 1) * 2];
                const unsigned* Bl = &bl[nt >> 1][(nt & 1) * 2];
                mma_bf16(acc[t][nt], ah[t], Bh);
                mma_bf16(acc[t][nt], ah[t], Bl);
                mma_bf16(acc[t][nt], al[t], Bh);
            }
        }

        if (it + 1 < niter) sstore((it + 1) & 1);
    }

    #pragma unroll
    for (int t = 0; t < 2; ++t) {
        int mB = row0 + wm * 32 + t * 16 + (lane >> 2);
        #pragma unroll
        for (int nt = 0; nt < 6; ++nt) {
            int nB = col0 + wn * 48 + nt * 8 + (lane & 3) * 2;
            float* c = acc[t][nt];
            #pragma unroll
            for (int e = 0; e < 4; ++e) {
                int gm = mB + (e >> 1) * 8;
                int gn = nB + (e & 1);
                if (gm < M && gn < N)
                    Cp[(size_t)gm * ldc + gn] = c[e];
            }
        }
    }
}

// ===========================================================================
// B-stage GEMM: 64x64 CTA tile, 128 threads, BK=16, double-buffered.
// M <= 64 always (M=50): row0 is FIXED at 0 — blockIdx.y belongs to callers
// (k_gemm_B2 uses it as the split-K chunk index).
// ===========================================================================
#define B_AP 24
#define B_BP 72

__device__ __forceinline__ void bgemmB(
    const float* __restrict__ A, int lda,
    const float* __restrict__ Bp, int ldb,
    float* __restrict__ Cp, int ldc,
    int M, int N, int K)
{
    __shared__ bf16 sAh[2][64][B_AP];
    __shared__ bf16 sAl[2][64][B_AP];
    __shared__ bf16 sBh[2][16][B_BP];
    __shared__ bf16 sBl[2][16][B_BP];

    const int tid  = threadIdx.x;
    const int lane = tid & 31;
    const int warp = tid >> 5;
    const int wm = warp & 1;              // 2 m-strips
    const int wn = warp >> 1;             // 2 n-halves
    const int row0 = 0;                   // M <= 64: single row tile (BUGFIX vs R10)
    const int col0 = blockIdx.x * 64;

    // gmem load mappings: 128 threads
    const int ar = tid >> 1;              // A row 0..63
    const int ac = (tid & 1) * 8;         // A k-offset 0/8 (2 float4)
    const int br = tid >> 3;              // B k-row 0..15
    const int bc = (tid & 7) * 8;         // B n-col (2 float4)

    float acc[2][4][4];
    #pragma unroll
    for (int t = 0; t < 2; ++t)
        #pragma unroll
        for (int n = 0; n < 4; ++n)
            #pragma unroll
            for (int e = 0; e < 4; ++e) acc[t][n][e] = 0.f;

    unsigned aAdH[2], aAdL[2], bAdH[2], bAdL[2];
    #pragma unroll
    for (int t = 0; t < 2; ++t) {
        int rr = wm * 32 + t * 16 + (lane & 15);
        int cc = (lane >> 4) * 8;
        aAdH[t] = (unsigned)__cvta_generic_to_shared(&sAh[0][rr][cc]);
        aAdL[t] = (unsigned)__cvta_generic_to_shared(&sAl[0][rr][cc]);
    }
    #pragma unroll
    for (int p = 0; p < 2; ++p) {
        int rr = (lane & 15);
        int cc = wn * 32 + p * 16 + (lane >> 4) * 8;
        bAdH[p] = (unsigned)__cvta_generic_to_shared(&sBh[0][rr][cc]);
        bAdL[p] = (unsigned)__cvta_generic_to_shared(&sBl[0][rr][cc]);
    }
    const unsigned aStg = 64u * B_AP * 2u;
    const unsigned bStg = 16u * B_BP * 2u;

    float4 av[2], bv[2];

    auto gload = [&](int kt) {
        int gr = row0 + ar;
        #pragma unroll
        for (int p = 0; p < 2; ++p)
            av[p] = (gr < M) ? *reinterpret_cast<const float4*>(&A[(size_t)gr * lda + kt + ac + p * 4])
                             : make_float4(0.f, 0.f, 0.f, 0.f);
        #pragma unroll
        for (int p = 0; p < 2; ++p) {
            int gc = col0 + bc + p * 4;
            bv[p] = (gc < N) ? *reinterpret_cast<const float4*>(&Bp[(size_t)(kt + br) * ldb + gc])
                             : make_float4(0.f, 0.f, 0.f, 0.f);
        }
    };

    auto sstore = [&](int s) {
        #pragma unroll
        for (int p = 0; p < 2; ++p) {
            bf16 h0,l0,h1,l1,h2,l2,h3,l3;
            f2bf(av[p].x, h0, l0); f2bf(av[p].y, h1, l1);
            f2bf(av[p].z, h2, l2); f2bf(av[p].w, h3, l3);
            __nv_bfloat162 q;
            int c = ac + p * 4;
            q.x = h0; q.y = h1; *reinterpret_cast<__nv_bfloat162*>(&sAh[s][ar][c])     = q;
            q.x = h2; q.y = h3; *reinterpret_cast<__nv_bfloat162*>(&sAh[s][ar][c + 2]) = q;
            q.x = l0; q.y = l1; *reinterpret_cast<__nv_bfloat162*>(&sAl[s][ar][c])     = q;
            q.x = l2; q.y = l3; *reinterpret_cast<__nv_bfloat162*>(&sAl[s][ar][c + 2]) = q;
        }
        #pragma unroll
        for (int p = 0; p < 2; ++p) {
            bf16 h0,l0,h1,l1,h2,l2,h3,l3;
            f2bf(bv[p].x, h0, l0); f2bf(bv[p].y, h1, l1);
            f2bf(bv[p].z, h2, l2); f2bf(bv[p].w, h3, l3);
            __nv_bfloat162 q;
            int c = bc + p * 4;
            q.x = h0; q.y = h1; *reinterpret_cast<__nv_bfloat162*>(&sBh[s][br][c])     = q;
            q.x = h2; q.y = h3; *reinterpret_cast<__nv_bfloat162*>(&sBh[s][br][c + 2]) = q;
            q.x = l0; q.y = l1; *reinterpret_cast<__nv_bfloat162*>(&sBl[s][br][c])     = q;
            q.x = l2; q.y = l3; *reinterpret_cast<__nv_bfloat162*>(&sBl[s][br][c + 2]) = q;
        }
    };

    const int niter = K / 16;
    gload(0);
    sstore(0);

    for (int it = 0; it < niter; ++it) {
        __syncthreads();
        if (it + 1 < niter) gload((it + 1) * 16);

        const int s = it & 1;
        const unsigned aOff = s * aStg, bOff = s * bStg;
        unsigned ah[2][4], al[2][4], bh[2][4], bl[2][4];
        #pragma unroll
        for (int t = 0; t < 2; ++t) {
            ldsm4(ah[t], aAdH[t] + aOff);
            ldsm4(al[t], aAdL[t] + aOff);
        }
        #pragma unroll
        for (int p = 0; p < 2; ++p) {
            ldsm4t(bh[p], bAdH[p] + bOff);
            ldsm4t(bl[p], bAdL[p] + bOff);
        }
        #pragma unroll
        for (int t = 0; t < 2; ++t) {
            #pragma unroll
            for (int nt = 0; nt < 4; ++nt) {
                const unsigned* Bh = &bh[nt >> 1][(nt & 1) * 2];
                const unsigned* Bl = &bl[nt >> 1][(nt & 1) * 2];
                mma_bf16(acc[t][nt], ah[t], Bh);
                mma_bf16(acc[t][nt], ah[t], Bl);
                mma_bf16(acc[t][nt], al[t], Bh);
            }
        }

        if (it + 1 < niter) sstore((it + 1) & 1);
    }

    #pragma unroll
    for (int t = 0; t < 2; ++t) {
        int mB = row0 + wm * 32 + t * 16 + (lane >> 2);
        #pragma unroll
        for (int nt = 0; nt < 4; ++nt) {
            int nB = col0 + wn * 32 + nt * 8 + (lane & 3) * 2;
            float* c = acc[t][nt];
            #pragma unroll
            for (int e = 0; e < 4; ++e) {
                int gm = mB + (e >> 1) * 8;
                int gn = nB + (e & 1);
                if (gm < M && gn < N)
                    Cp[(size_t)gm * ldc + gn] = c[e];
            }
        }
    }
}

// ---------------------------------------------------------------------------
// Stage kernels
// ---------------------------------------------------------------------------
__global__ void __launch_bounds__(384) k_gemm_A1(const float* __restrict__ R,
                                                 const float* __restrict__ x) {
    const int z = blockIdx.z;
    const int j = z % Cn;
    const int i = (z / Cn) % Cn;
    const int b = z / (Cn * Cn);
    const float* A  = R   + (size_t)(i * Cn + j) * Dn * Dn;
    const float* Bp = x   + (size_t)(b * Cn + j) * Dn * Dn;
    float*       Cp = g_t + (size_t)(b * Cn + i) * Dn * Kbig + (size_t)j * Dn;
    bgemmA(A, Dn, Bp, Dn, Cp, Kbig, Dn, Dn, Dn);
}

__global__ void __launch_bounds__(384) k_gemm_A2() {
    const int z = blockIdx.z;                 // b*Cn + i
    const int i = z % Cn;
    const float* A  = g_t  + (size_t)z * Dn * Kbig;
    const float* Bp = g_Rt + (size_t)i * Cn * Dn * Dn;
    float*       Cp = g_y  + (size_t)z * Dn * Dn;
    bgemmA(A, Kbig, Bp, Dn, Cp, Dn, Dn, Dn, Kbig);
}

__global__ void __launch_bounds__(128) k_gemm_B1(const float* __restrict__ P) {
    const int z = blockIdx.z;                 // (b*OCn + i)*Cn + j
    const int j = z % Cn;
    const int i = (z / Cn) % OCn;
    const int b = z / (Cn * OCn);
    const float* A  = P   + (size_t)(i * Cn + j) * OHn * Dn;
    const float* Bp = g_y + (size_t)(b * Cn + j) * Dn * Dn;
    float*       Cp = g_u + (size_t)(b * OCn + i) * OHn * Kbig + (size_t)j * Dn;
    bgemmB(A, Dn, Bp, Dn, Cp, Kbig, OHn, Dn, Dn);
}

// B2 split-K: blockIdx.y = k-chunk (4 chunks of 768); writes fp32 partials.
__global__ void __launch_bounds__(128) k_gemm_B2(const float* __restrict__ PT) {
    const int z  = blockIdx.z;                // b*OCn + i
    const int ky = blockIdx.y;                // 0..3 (split-K chunk)
    const int i  = z % OCn;
    const int kt0 = ky * (Kbig / 4);          // 768
    const float* A  = g_u + (size_t)z * OHn * Kbig + kt0;
    const float* Bp = PT  + (size_t)i * (size_t)Kbig * OWn + (size_t)kt0 * OWn;
    float*       Cp = g_p + ((size_t)ky * (Bn * OCn) + z) * OHn * OWn;
    bgemmB(A, Kbig, Bp, OWn, Cp, OWn, OHn, OWn, Kbig / 4);
}

// Sum the 4 partials (fixed order -> deterministic)
__global__ void k_reduce(float* __restrict__ out) {
    const size_t n = (size_t)Bn * OCn * OHn * OWn;     // 320000
    size_t idx = (size_t)blockIdx.x * blockDim.x + threadIdx.x;
    if (idx >= n) return;
    float s = g_p[idx];
    s += g_p[n + idx];
    s += g_p[2 * n + idx];
    s += g_p[3 * n + idx];
    out[idx] = s;
}

// ---------------------------------------------------------------------------
extern "C" void kernel_launch(void* const* d_in, const int* in_sizes, int n_in,
                              void* d_out, int out_size) {
    const float* x  = (const float*)d_in[0];
    const float* R  = (const float*)d_in[1];
    const float* P  = (const float*)d_in[2];
    const float* PT = (const float*)d_in[3];
    float* out = (float*)d_out;

    k_transpose<<<dim3(6, 6, 256), dim3(32, 8)>>>(R);
    k_gemm_A1<<<dim3(2, 1, Bn * Cn * Cn), 384>>>(R, x);
    k_gemm_A2<<<dim3(2, 1, Bn * Cn), 384>>>();
    k_gemm_B1<<<dim3(3, 1, Bn * OCn * Cn), 128>>>(P);
    k_gemm_B2<<<dim3(4, 4, Bn * OCn), 128>>>(PT);
    k_reduce<<<(Bn * OCn * OHn * OWn + 255) / 256, 256>>>(out);
}